// round 7
// baseline (speedup 1.0000x reference)
#include <cuda_runtime.h>
#include <cuda_bf16.h>
#include <cstdint>

// ---------------------------------------------------------------------------
// BlockwiseToPixels: token-routed MoE linear.
//   out[t, :] = x[t, :] @ W[idx[t]] + b[idx[t]]
// Strategy: sort tokens by expert (histogram -> scan -> scatter), then grouped
// tf32 tensor-core GEMM per 128-token tile of a single expert.
// ---------------------------------------------------------------------------

#define D_DIM 256
#define P_DIM 64
#define E_NUM 16
#define TILE_M 128
#define NTOK_MAX 262144
#define MAX_TILES (NTOK_MAX / TILE_M + E_NUM)   // 2064
#define PERM_CAP (MAX_TILES * TILE_M)

#define SX_STRIDE 260   // 256 + 4 pad -> conflict-free A fragment loads
#define SW_STRIDE 72    // 64 + 8 pad  -> conflict-free B fragment loads

// Scratch (allocation-free rule: __device__ globals)
__device__ int g_perm[PERM_CAP];
__device__ int g_cnt[E_NUM];
__device__ int g_cur[E_NUM];
__device__ int g_off[E_NUM + 1];

// ---------------------------------------------------------------------------
__global__ void init_kernel() {
    int i = blockIdx.x * blockDim.x + threadIdx.x;
    if (i < PERM_CAP) g_perm[i] = -1;
    if (i < E_NUM) { g_cnt[i] = 0; g_cur[i] = 0; }
}

__global__ void hist_kernel(const int* __restrict__ idx, int n) {
    __shared__ int sh[E_NUM];
    if (threadIdx.x < E_NUM) sh[threadIdx.x] = 0;
    __syncthreads();
    for (int i = blockIdx.x * blockDim.x + threadIdx.x; i < n;
         i += gridDim.x * blockDim.x)
        atomicAdd(&sh[idx[i]], 1);
    __syncthreads();
    if (threadIdx.x < E_NUM) atomicAdd(&g_cnt[threadIdx.x], sh[threadIdx.x]);
}

__global__ void scan_kernel() {
    int run = 0;
    for (int e = 0; e < E_NUM; e++) {
        g_off[e] = run;
        run += ((g_cnt[e] + TILE_M - 1) / TILE_M) * TILE_M;  // pad to tile
    }
    g_off[E_NUM] = run;
}

__global__ void scatter_kernel(const int* __restrict__ idx, int n) {
    __shared__ int s_cnt[E_NUM];
    __shared__ int s_base[E_NUM];
    if (threadIdx.x < E_NUM) s_cnt[threadIdx.x] = 0;
    __syncthreads();
    int t = blockIdx.x * blockDim.x + threadIdx.x;
    int e = 0, my = 0;
    if (t < n) { e = idx[t]; my = atomicAdd(&s_cnt[e], 1); }
    __syncthreads();
    if (threadIdx.x < E_NUM)
        s_base[threadIdx.x] = atomicAdd(&g_cur[threadIdx.x], s_cnt[threadIdx.x]);
    __syncthreads();
    if (t < n) g_perm[g_off[e] + s_base[e] + my] = t;
}

// ---------------------------------------------------------------------------
__device__ __forceinline__ float to_tf32(float x) {
    float r;
    asm("cvt.rna.tf32.f32 %0, %1;" : "=f"(r) : "f"(x));
    return r;
}

__global__ void __launch_bounds__(256, 1) gemm_kernel(
    const float* __restrict__ x, const float* __restrict__ W,
    const float* __restrict__ b, float* __restrict__ out)
{
    extern __shared__ float smem[];
    float* sx   = smem;                               // 128 x 260
    float* sw   = sx + TILE_M * SX_STRIDE;            // 256 x 72
    float* sb   = sw + D_DIM * SW_STRIDE;             // 64
    int*   sperm = (int*)(sb + P_DIM);                // 128

    int base = blockIdx.x * TILE_M;
    if (base >= g_off[E_NUM]) return;

    int e = 0;
    while (g_off[e + 1] <= base) e++;   // 16 entries max, uniform per block

    int tid = threadIdx.x;
    if (tid < TILE_M) sperm[tid] = g_perm[base + tid];
    if (tid >= TILE_M && tid < TILE_M + P_DIM)
        sb[tid - TILE_M] = b[e * P_DIM + (tid - TILE_M)];

    // W[e] (256x64 f32) -> smem [k][n] stride 72, tf32-rounded
    const float4* Wv = (const float4*)(W + e * D_DIM * P_DIM);
    for (int i = tid; i < D_DIM * P_DIM / 4; i += 256) {
        float4 v = Wv[i];
        int el = i * 4;
        int k = el >> 6;    // /64
        int n = el & 63;
        float4 c;
        c.x = to_tf32(v.x); c.y = to_tf32(v.y);
        c.z = to_tf32(v.z); c.w = to_tf32(v.w);
        *(float4*)(sw + k * SW_STRIDE + n) = c;
    }
    __syncthreads();   // sperm ready before gather

    // gather x rows (1KB each, fully coalesced float4)
    const float4* xv = (const float4*)x;
    for (int i = tid; i < TILE_M * (D_DIM / 4); i += 256) {
        int row = i >> 6;   // /(256/4)
        int c4  = i & 63;
        int t = sperm[row];
        float4 c;
        if (t >= 0) {
            float4 v = xv[t * (D_DIM / 4) + c4];
            c.x = to_tf32(v.x); c.y = to_tf32(v.y);
            c.z = to_tf32(v.z); c.w = to_tf32(v.w);
        } else {
            c.x = c.y = c.z = c.w = 0.f;
        }
        *(float4*)(sx + row * SX_STRIDE + c4 * 4) = c;
    }
    __syncthreads();

    // each warp: 16 rows x 64 cols, K=256 in k8 steps via mma.m16n8k8.tf32
    int warp = tid >> 5, lane = tid & 31;
    int g = lane >> 2, tg = lane & 3;
    int row0 = warp * 16 + g;
    const float* A0 = sx + row0 * SX_STRIDE;
    const float* A1 = A0 + 8 * SX_STRIDE;

    float acc[8][4];
    #pragma unroll
    for (int nt = 0; nt < 8; nt++)
        acc[nt][0] = acc[nt][1] = acc[nt][2] = acc[nt][3] = 0.f;

    #pragma unroll 4
    for (int k0 = 0; k0 < D_DIM; k0 += 8) {
        unsigned a0 = __float_as_uint(A0[k0 + tg]);
        unsigned a1 = __float_as_uint(A1[k0 + tg]);
        unsigned a2 = __float_as_uint(A0[k0 + tg + 4]);
        unsigned a3 = __float_as_uint(A1[k0 + tg + 4]);
        const float* B0 = sw + (k0 + tg) * SW_STRIDE + g;
        const float* B1 = B0 + 4 * SW_STRIDE;
        #pragma unroll
        for (int nt = 0; nt < 8; nt++) {
            unsigned b0 = __float_as_uint(B0[nt * 8]);
            unsigned b1 = __float_as_uint(B1[nt * 8]);
            asm volatile(
                "mma.sync.aligned.m16n8k8.row.col.f32.tf32.tf32.f32 "
                "{%0,%1,%2,%3}, {%4,%5,%6,%7}, {%8,%9}, {%0,%1,%2,%3};"
                : "+f"(acc[nt][0]), "+f"(acc[nt][1]),
                  "+f"(acc[nt][2]), "+f"(acc[nt][3])
                : "r"(a0), "r"(a1), "r"(a2), "r"(a3), "r"(b0), "r"(b1));
        }
    }

    // epilogue: bias + scattered float2 stores (contiguous 32B per 4 lanes)
    int t0 = sperm[row0];
    int t1 = sperm[row0 + 8];
    #pragma unroll
    for (int nt = 0; nt < 8; nt++) {
        int n = nt * 8 + 2 * tg;
        float bn0 = sb[n], bn1 = sb[n + 1];
        if (t0 >= 0) {
            float2 v; v.x = acc[nt][0] + bn0; v.y = acc[nt][1] + bn1;
            *(float2*)(out + t0 * P_DIM + n) = v;
        }
        if (t1 >= 0) {
            float2 v; v.x = acc[nt][2] + bn0; v.y = acc[nt][3] + bn1;
            *(float2*)(out + t1 * P_DIM + n) = v;
        }
    }
}

// ---------------------------------------------------------------------------
// Generic fallback (only if shapes differ from the expected problem instance)
__global__ void fallback_kernel(const float* __restrict__ x,
                                const float* __restrict__ W,
                                const float* __restrict__ b,
                                const int* __restrict__ idx,
                                float* __restrict__ out,
                                int n, int D, int P) {
    int t = blockIdx.x;
    int p = threadIdx.x;
    if (t >= n || p >= P) return;
    int e = idx[t];
    float s = b[(long)e * P + p];
    const float* xr = x + (long)t * D;
    const float* wc = W + (long)e * D * P + p;
    for (int d = 0; d < D; d++) s += xr[d] * wc[(long)d * P];
    out[(long)t * P + p] = s;
}

// ---------------------------------------------------------------------------
extern "C" void kernel_launch(void* const* d_in, const int* in_sizes, int n_in,
                              void* d_out, int out_size) {
    const float* x   = (const float*)d_in[0];
    const float* W   = (const float*)d_in[1];
    const float* b   = (const float*)d_in[2];
    const int*   idx = (const int*)d_in[3];
    float* out = (float*)d_out;

    int n_tok = in_sizes[3];
    int D = (n_tok > 0) ? in_sizes[0] / n_tok : 0;
    int P = (n_tok > 0) ? out_size / n_tok : 0;
    int E = (P > 0) ? in_sizes[2] / P : 0;

    if (D != D_DIM || P != P_DIM || E != E_NUM || n_tok > NTOK_MAX) {
        fallback_kernel<<<n_tok, (P > 0 ? P : 1)>>>(x, W, b, idx, out, n_tok, D, P);
        return;
    }

    init_kernel<<<(PERM_CAP + 255) / 256, 256>>>();
    hist_kernel<<<512, 256>>>(idx, n_tok);
    scan_kernel<<<1, 1>>>();
    scatter_kernel<<<(n_tok + 255) / 256, 256>>>(idx, n_tok);

    constexpr int SMEM_BYTES =
        (TILE_M * SX_STRIDE + D_DIM * SW_STRIDE + P_DIM) * 4 + TILE_M * 4;
    cudaFuncSetAttribute(gemm_kernel,
                         cudaFuncAttributeMaxDynamicSharedMemorySize, SMEM_BYTES);
    gemm_kernel<<<MAX_TILES, 256, SMEM_BYTES>>>(x, W, b, out);
}

// round 10
// speedup vs baseline: 1.7011x; 1.7011x over previous
#include <cuda_runtime.h>
#include <cuda_bf16.h>
#include <cstdint>

// ---------------------------------------------------------------------------
// BlockwiseToPixels: token-routed MoE linear.
//   out[t, :] = x[t, :] @ W[idx[t]] + b[idx[t]]
// R8: sort-by-expert + grouped tf32 GEMM, TILE_M=256, K-chunked smem (KC=64)
// for 2 CTAs/SM, 32x64 warp tiles (B fragments amortized over 2 row-tiles).
// ---------------------------------------------------------------------------

#define D_DIM 256
#define P_DIM 64
#define E_NUM 16
#define TILE_M 256
#define KC 64
#define NTOK_MAX 262144
#define MAX_TILES (NTOK_MAX / TILE_M + E_NUM)   // 1040
#define PERM_CAP (MAX_TILES * TILE_M)

#define SXS 68   // KC + 4 pad  -> A fragment loads: bank 4g+tg, conflict-free
#define SWS 72   // 64 + 8 pad  -> B fragment loads: bank 8tg+g, conflict-free

// Scratch (allocation-free rule: __device__ globals)
__device__ int g_perm[PERM_CAP];
__device__ int g_cnt[E_NUM];
__device__ int g_cur[E_NUM];
__device__ int g_off[E_NUM + 1];

// ---------------------------------------------------------------------------
__global__ void init_kernel() {
    int i = threadIdx.x;
    if (i < E_NUM) { g_cnt[i] = 0; g_cur[i] = 0; }
}

__global__ void hist_kernel(const int* __restrict__ idx, int n) {
    __shared__ int sh[E_NUM];
    if (threadIdx.x < E_NUM) sh[threadIdx.x] = 0;
    __syncthreads();
    for (int i = blockIdx.x * blockDim.x + threadIdx.x; i < n;
         i += gridDim.x * blockDim.x)
        atomicAdd(&sh[idx[i]], 1);
    __syncthreads();
    if (threadIdx.x < E_NUM) atomicAdd(&g_cnt[threadIdx.x], sh[threadIdx.x]);
}

__global__ void scan_kernel() {
    int run = 0;
    for (int e = 0; e < E_NUM; e++) {
        g_off[e] = run;
        run += ((g_cnt[e] + TILE_M - 1) / TILE_M) * TILE_M;  // pad to tile
    }
    g_off[E_NUM] = run;
}

__global__ void scatter_kernel(const int* __restrict__ idx, int n) {
    __shared__ int s_cnt[E_NUM];
    __shared__ int s_base[E_NUM];
    if (threadIdx.x < E_NUM) s_cnt[threadIdx.x] = 0;
    __syncthreads();
    int t = blockIdx.x * blockDim.x + threadIdx.x;
    int e = 0, my = 0;
    if (t < n) { e = idx[t]; my = atomicAdd(&s_cnt[e], 1); }
    __syncthreads();
    if (threadIdx.x < E_NUM)
        s_base[threadIdx.x] = atomicAdd(&g_cur[threadIdx.x], s_cnt[threadIdx.x]);
    __syncthreads();
    if (t < n) g_perm[g_off[e] + s_base[e] + my] = t;
}

// ---------------------------------------------------------------------------
__device__ __forceinline__ float to_tf32(float x) {
    float r;
    asm("cvt.rna.tf32.f32 %0, %1;" : "=f"(r) : "f"(x));
    return r;
}

__global__ void __launch_bounds__(256, 2) gemm_kernel(
    const float* __restrict__ x, const float* __restrict__ W,
    const float* __restrict__ b, float* __restrict__ out)
{
    extern __shared__ float smem[];
    float* sx    = smem;                       // 256 x 68
    float* sw    = sx + TILE_M * SXS;          // 64 x 72
    float* sb    = sw + KC * SWS;              // 64
    int*   sperm = (int*)(sb + P_DIM);         // 256

    int base = blockIdx.x * TILE_M;
    if (base >= g_off[E_NUM]) return;

    int e = 0;
    while (g_off[e + 1] <= base) e++;   // uniform per block, <=16 iters

    int tid = threadIdx.x;
    int cnt = g_cnt[e];
    {   // pad rows (beyond this expert's real token count) -> -1
        int local = base + tid - g_off[e];
        sperm[tid] = (local < cnt) ? g_perm[base + tid] : -1;
    }
    if (tid < P_DIM) sb[tid] = b[e * P_DIM + tid];

    int warp = tid >> 5, lane = tid & 31;
    int g = lane >> 2, tg = lane & 3;
    int row0 = warp * 32 + g;              // 8 warps x 32 rows

    float acc[2][8][4];
    #pragma unroll
    for (int rt = 0; rt < 2; rt++)
        #pragma unroll
        for (int nt = 0; nt < 8; nt++)
            acc[rt][nt][0] = acc[rt][nt][1] = acc[rt][nt][2] = acc[rt][nt][3] = 0.f;

    const float4* xv = (const float4*)x;
    const float4* Wv = (const float4*)(W + e * D_DIM * P_DIM);

    for (int c = 0; c < D_DIM / KC; c++) {
        __syncthreads();   // smem reuse + (c==0) sperm visibility

        // W chunk: rows c*64..c*64+63 of W[e] -> sw[kl][n], tf32
        for (int i4 = tid; i4 < KC * P_DIM / 4; i4 += 256) {
            int el = i4 * 4;
            int kl = el >> 6;
            int n  = el & 63;
            float4 v = Wv[((c * KC + kl) * P_DIM + n) >> 2];
            float4 cv;
            cv.x = to_tf32(v.x); cv.y = to_tf32(v.y);
            cv.z = to_tf32(v.z); cv.w = to_tf32(v.w);
            *(float4*)(sw + kl * SWS + n) = cv;
        }

        // x chunk gather: 256 rows x 64 cols (16 float4/row, coalesced)
        for (int i4 = tid; i4 < TILE_M * (KC / 4); i4 += 256) {
            int row = i4 >> 4;
            int c4  = i4 & 15;
            int t = sperm[row];
            float4 cv;
            if (t >= 0) {
                float4 v = xv[t * (D_DIM / 4) + c * (KC / 4) + c4];
                cv.x = to_tf32(v.x); cv.y = to_tf32(v.y);
                cv.z = to_tf32(v.z); cv.w = to_tf32(v.w);
            } else {
                cv.x = cv.y = cv.z = cv.w = 0.f;
            }
            *(float4*)(sx + row * SXS + c4 * 4) = cv;
        }
        __syncthreads();

        #pragma unroll
        for (int k0 = 0; k0 < KC; k0 += 8) {
            unsigned a[2][4];
            #pragma unroll
            for (int rt = 0; rt < 2; rt++) {
                const float* Ar = sx + (row0 + rt * 16) * SXS;
                a[rt][0] = __float_as_uint(Ar[k0 + tg]);
                a[rt][1] = __float_as_uint(Ar[8 * SXS + k0 + tg]);
                a[rt][2] = __float_as_uint(Ar[k0 + tg + 4]);
                a[rt][3] = __float_as_uint(Ar[8 * SXS + k0 + tg + 4]);
            }
            const float* B0 = sw + (k0 + tg) * SWS + g;
            #pragma unroll
            for (int nt = 0; nt < 8; nt++) {
                unsigned b0 = __float_as_uint(B0[nt * 8]);
                unsigned b1 = __float_as_uint(B0[4 * SWS + nt * 8]);
                #pragma unroll
                for (int rt = 0; rt < 2; rt++) {
                    asm volatile(
                        "mma.sync.aligned.m16n8k8.row.col.f32.tf32.tf32.f32 "
                        "{%0,%1,%2,%3}, {%4,%5,%6,%7}, {%8,%9}, {%0,%1,%2,%3};"
                        : "+f"(acc[rt][nt][0]), "+f"(acc[rt][nt][1]),
                          "+f"(acc[rt][nt][2]), "+f"(acc[rt][nt][3])
                        : "r"(a[rt][0]), "r"(a[rt][1]),
                          "r"(a[rt][2]), "r"(a[rt][3]),
                          "r"(b0), "r"(b1));
                }
            }
        }
    }

    // epilogue: bias + scattered float2 stores (4 lanes -> contiguous 32B)
    #pragma unroll
    for (int rt = 0; rt < 2; rt++) {
        int r0 = row0 + rt * 16;
        int t0 = sperm[r0];
        int t1 = sperm[r0 + 8];
        #pragma unroll
        for (int nt = 0; nt < 8; nt++) {
            int n = nt * 8 + 2 * tg;
            float bn0 = sb[n], bn1 = sb[n + 1];
            if (t0 >= 0) {
                float2 v; v.x = acc[rt][nt][0] + bn0; v.y = acc[rt][nt][1] + bn1;
                *(float2*)(out + t0 * P_DIM + n) = v;
            }
            if (t1 >= 0) {
                float2 v; v.x = acc[rt][nt][2] + bn0; v.y = acc[rt][nt][3] + bn1;
                *(float2*)(out + t1 * P_DIM + n) = v;
            }
        }
    }
}

// ---------------------------------------------------------------------------
// Generic fallback (only if shapes differ from the expected problem instance)
__global__ void fallback_kernel(const float* __restrict__ x,
                                const float* __restrict__ W,
                                const float* __restrict__ b,
                                const int* __restrict__ idx,
                                float* __restrict__ out,
                                int n, int D, int P) {
    int t = blockIdx.x;
    int p = threadIdx.x;
    if (t >= n || p >= P) return;
    int e = idx[t];
    float s = b[(long)e * P + p];
    const float* xr = x + (long)t * D;
    const float* wc = W + (long)e * D * P + p;
    for (int d = 0; d < D; d++) s += xr[d] * wc[(long)d * P];
    out[(long)t * P + p] = s;
}

// ---------------------------------------------------------------------------
extern "C" void kernel_launch(void* const* d_in, const int* in_sizes, int n_in,
                              void* d_out, int out_size) {
    const float* x   = (const float*)d_in[0];
    const float* W   = (const float*)d_in[1];
    const float* b   = (const float*)d_in[2];
    const int*   idx = (const int*)d_in[3];
    float* out = (float*)d_out;

    int n_tok = in_sizes[3];
    int D = (n_tok > 0) ? in_sizes[0] / n_tok : 0;
    int P = (n_tok > 0) ? out_size / n_tok : 0;
    int E = (P > 0) ? in_sizes[2] / P : 0;

    if (D != D_DIM || P != P_DIM || E != E_NUM || n_tok > NTOK_MAX) {
        fallback_kernel<<<n_tok, (P > 0 ? P : 1)>>>(x, W, b, idx, out, n_tok, D, P);
        return;
    }

    init_kernel<<<1, 32>>>();
    hist_kernel<<<512, 256>>>(idx, n_tok);
    scan_kernel<<<1, 1>>>();
    scatter_kernel<<<(n_tok + 255) / 256, 256>>>(idx, n_tok);

    constexpr int SMEM_BYTES =
        (TILE_M * SXS + KC * SWS + P_DIM) * 4 + TILE_M * 4;   // 89344
    cudaFuncSetAttribute(gemm_kernel,
                         cudaFuncAttributeMaxDynamicSharedMemorySize, SMEM_BYTES);
    gemm_kernel<<<MAX_TILES, 256, SMEM_BYTES>>>(x, W, b, out);
}